// round 12
// baseline (speedup 1.0000x reference)
#include <cuda_runtime.h>
#include <math.h>
#include <stdint.h>

// Problem constants
#define TK   16384        // total tokens (8 * 2048)
#define DM   1024         // d_model
#define DF   4096         // d_ff
#define NE   8            // experts
#define CAPC 2048         // capacity

// int8 scaling (powers of 2 — exact in fp32)
#define XSCALE   16.0f            // tokens scaled before s8 quantization
#define W1SCALE  4096.0f          // w1 scaled before s8 quantization
#define W2SCALE  8192.0f          // w2 scaled before s8 quantization
#define HSCALE   128.0f           // hidden acts scaled before s8 quantization
#define INV_XW1  (1.0f / (16.0f * 4096.0f))
#define INV_HW2  (1.0f / (128.0f * 8192.0f))

// GEMM tiling (Ampere-style s8 IMMA mma.sync path — compute_103-safe)
#define BM   128
#define BN   256
#define KBLK 128                        // K elems per stage: 128 s8 = 128B row
#define NS   3                          // cp.async pipeline stages
#define A_BYTES (BM * 128)              // 16384
#define B_BYTES (BN * 128)              // 32768
#define STAGE_BYTES (A_BYTES + B_BYTES) // 49152
#define SMEM_TOTAL (NS * STAGE_BYTES)   // 147456

// ---------------- scratch ---------------------------------------------------
__device__ int8_t g_expert_in[(size_t)NE * CAPC * DM];  // s8 tokens x XSCALE
__device__ int8_t g_H[(size_t)TK * DF];                 // s8 hidden acts x HSCALE
__device__ int8_t g_W1t[(size_t)NE * DF * DM];          // s8 W1^T x W1SCALE
__device__ int8_t g_W2t[(size_t)NE * DM * DF];          // s8 W2^T x W2SCALE
__device__ int   g_slot_token[NE * CAPC];
__device__ int   g_top1_idx[TK];
__device__ float g_top1_prob[TK];
__device__ int   g_fits[TK];
__device__ float g_Pi[NE];
__device__ float g_zsum;
__device__ int   g_counts[NE];

// ---------------- helpers ---------------------------------------------------
__device__ __forceinline__ uint32_t smem_u32(const void* p) {
    uint32_t a;
    asm("{ .reg .u64 t; cvta.to.shared.u64 t, %1; cvt.u32.u64 %0, t; }" : "=r"(a) : "l"(p));
    return a;
}
__device__ __forceinline__ int q8i(float x) {      // round + clamp to [-127,127]
    int v = __float2int_rn(x);
    return max(-127, min(127, v));
}
__device__ __forceinline__ uint32_t pack4_s8(int a, int b, int c, int d) {
    return (uint32_t)(a & 0xFF) | ((uint32_t)(b & 0xFF) << 8) |
           ((uint32_t)(c & 0xFF) << 16) | ((uint32_t)(d & 0xFF) << 24);
}
__device__ __forceinline__ void cp16(uint32_t sm, const void* g) {
    asm volatile("cp.async.cg.shared.global [%0], [%1], 16;" :: "r"(sm), "l"(g));
}
#define CP_COMMIT() asm volatile("cp.async.commit_group;" ::: "memory")
#define CP_WAIT(n)  asm volatile("cp.async.wait_group %0;" :: "n"(n) : "memory")

__device__ __forceinline__ void ldsm4(uint32_t& r0, uint32_t& r1, uint32_t& r2,
                                      uint32_t& r3, uint32_t addr) {
    asm volatile("ldmatrix.sync.aligned.m8n8.x4.shared.b16 {%0,%1,%2,%3}, [%4];"
                 : "=r"(r0), "=r"(r1), "=r"(r2), "=r"(r3) : "r"(addr));
}
__device__ __forceinline__ void mma_s8(int* d, const uint32_t* a, const uint32_t* b) {
    asm volatile(
        "mma.sync.aligned.m16n8k32.row.col.s32.s8.s8.s32 "
        "{%0,%1,%2,%3}, {%4,%5,%6,%7}, {%8,%9}, {%0,%1,%2,%3};"
        : "+r"(d[0]), "+r"(d[1]), "+r"(d[2]), "+r"(d[3])
        : "r"(a[0]), "r"(a[1]), "r"(a[2]), "r"(a[3]), "r"(b[0]), "r"(b[1]));
}

// ---------------- init ------------------------------------------------------
__global__ void init_kernel() {
    int i = blockIdx.x * blockDim.x + threadIdx.x;
    if (i < NE * CAPC) g_slot_token[i] = -1;
    if (i < NE) g_Pi[i] = 0.f;
    if (i == 0) g_zsum = 0.f;
}

// ---------------- router ----------------------------------------------------
__global__ void router_kernel(const float* __restrict__ x,
                              const float* __restrict__ wr) {
    __shared__ float s_wr[DM * NE];
    __shared__ float s_pi[NE];
    __shared__ float s_z;
    for (int i = threadIdx.x; i < DM * NE; i += blockDim.x) s_wr[i] = wr[i];
    if (threadIdx.x < NE) s_pi[threadIdx.x] = 0.f;
    if (threadIdx.x == 0) s_z = 0.f;
    __syncthreads();

    int warp = threadIdx.x >> 5, lane = threadIdx.x & 31;
    int gw = blockIdx.x * (blockDim.x >> 5) + warp;
    int nw = gridDim.x * (blockDim.x >> 5);
    for (int t = gw; t < TK; t += nw) {
        const float* xt = x + (size_t)t * DM;
        float acc[NE];
#pragma unroll
        for (int e = 0; e < NE; e++) acc[e] = 0.f;
        for (int k = lane; k < DM; k += 32) {
            float xv = xt[k];
#pragma unroll
            for (int e = 0; e < NE; e++) acc[e] += xv * s_wr[k * NE + e];
        }
#pragma unroll
        for (int e = 0; e < NE; e++) {
#pragma unroll
            for (int off = 16; off; off >>= 1)
                acc[e] += __shfl_xor_sync(0xffffffffu, acc[e], off);
        }
        if (lane == 0) {
            float mx = acc[0]; int mi = 0;
#pragma unroll
            for (int e = 1; e < NE; e++) if (acc[e] > mx) { mx = acc[e]; mi = e; }
            float p[NE]; float se = 0.f;
#pragma unroll
            for (int e = 0; e < NE; e++) { p[e] = expf(acc[e] - mx); se += p[e]; }
            float inv = 1.f / se;
            g_top1_idx[t]  = mi;
            g_top1_prob[t] = inv;
#pragma unroll
            for (int e = 0; e < NE; e++) atomicAdd(&s_pi[e], p[e] * inv);
            float lse = mx + logf(se);
            atomicAdd(&s_z, lse * lse);
        }
    }
    __syncthreads();
    if (threadIdx.x < NE) atomicAdd(&g_Pi[threadIdx.x], s_pi[threadIdx.x]);
    if (threadIdx.x == 32) atomicAdd(&g_zsum, s_z);
}

// ---------------- FCFS capacity assignment ---------------------------------
__global__ void assign_kernel() {
    __shared__ int s_cnt[256 * NE];
    int tid = threadIdx.x;
#pragma unroll
    for (int e = 0; e < NE; e++) s_cnt[tid * NE + e] = 0;
    const int CHUNK = TK / 256;
    int base = tid * CHUNK;
    for (int i = 0; i < CHUNK; i++) s_cnt[tid * NE + g_top1_idx[base + i]]++;
    __syncthreads();
    if (tid < NE) {
        int run = 0;
        for (int i = 0; i < 256; i++) {
            int v = s_cnt[i * NE + tid];
            s_cnt[i * NE + tid] = run;
            run += v;
        }
        g_counts[tid] = run;
    }
    __syncthreads();
    for (int i = 0; i < CHUNK; i++) {
        int t = base + i;
        int e = g_top1_idx[t];
        int p = s_cnt[tid * NE + e]++;
        int f = (p < CAPC);
        g_fits[t] = f;
        if (f) g_slot_token[e * CAPC + p] = t;
    }
}

// ---------------- dispatch (fp32 -> s8 x XSCALE) ----------------------------
__global__ void dispatch_kernel(const float* __restrict__ x) {
    int s = blockIdx.x;
    int t = g_slot_token[s];
    uint32_t* dst = reinterpret_cast<uint32_t*>(g_expert_in + (size_t)s * DM);
    if (t >= 0) {
        float4 v = reinterpret_cast<const float4*>(x + (size_t)t * DM)[threadIdx.x];
        dst[threadIdx.x] = pack4_s8(q8i(v.x * XSCALE), q8i(v.y * XSCALE),
                                    q8i(v.z * XSCALE), q8i(v.w * XSCALE));
    } else {
        dst[threadIdx.x] = 0u;
    }
}

// ---------------- passthrough for dropped tokens only -----------------------
__global__ void dropped_copy_kernel(const float* __restrict__ x, float* __restrict__ out) {
    int t = blockIdx.x;
    if (g_fits[t]) return;
    reinterpret_cast<float4*>(out + (size_t)t * DM)[threadIdx.x] =
        reinterpret_cast<const float4*>(x + (size_t)t * DM)[threadIdx.x];
}

// ---------------- weight transpose [E][K][N] -> [E][N][K] s8 x SCALE --------
__global__ void transpose_kernel(const float* __restrict__ src,
                                 int8_t* __restrict__ dst,
                                 int K, int N, float scale) {
    __shared__ float tile[32][33];
    int e = blockIdx.z;
    int k0 = blockIdx.y * 32, n0 = blockIdx.x * 32;
    src += (size_t)e * K * N;
    dst += (size_t)e * N * K;
#pragma unroll
    for (int i = threadIdx.y; i < 32; i += 8)
        tile[i][threadIdx.x] = src[(size_t)(k0 + i) * N + n0 + threadIdx.x];
    __syncthreads();
#pragma unroll
    for (int i = threadIdx.y; i < 32; i += 8)
        dst[(size_t)(n0 + i) * K + k0 + threadIdx.x] =
            (int8_t)q8i(tile[threadIdx.x][i] * scale);
}

// ---------------- s8 IMMA mma.sync GEMM -------------------------------------
// C[16384, NTOT] = A[16384, K] * Bt_e[NTOT, K]^T  (per-expert weights, s8)
// CTA 128x256; 16 warps in 4x4 grid, each 32x64. k-block = 128 elems (128B row).
// EP=0: H = s8(relu(acc*INV_XW1 + b1) * HSCALE)
// EP=1: scatter (acc*INV_HW2 + b2)*prob -> out (fp32)
template <int K, int NTOT, int EP>
__global__ __launch_bounds__(512, 1) void moe_gemm(
    const int8_t* __restrict__ Bt, const float* __restrict__ bias,
    float* __restrict__ outp) {
    extern __shared__ char smem[];
    const uint32_t sb = smem_u32(smem);
    const int tid = threadIdx.x, wid = tid >> 5, lane = tid & 31;
    constexpr int KT = K / KBLK;

    const int8_t* A = (EP == 0) ? g_expert_in : g_H;
    const int cCol = blockIdx.x, cRow = blockIdx.y;
    const int expert = cRow >> 4;                 // 2048 rows / 128 per expert
    const int aRow0 = cRow * BM;
    const int bRow0 = expert * NTOT + cCol * BN;
    const int warpM = (wid >> 2) * 32;            // 0,32,64,96
    const int warpN = (wid & 3) * 64;             // 0..192

    // cp.async per-thread pattern: 16B chunks (16 s8), swizzled smem targets
    // 512 threads: A = 2 chunks, B = 4 chunks per stage
    uint32_t swzA[2], swzB[4];
    const int8_t* gA[2];
    const int8_t* gB[4];
#pragma unroll
    for (int i = 0; i < 2; i++) {
        int q = tid + i * 512, r = q >> 3, c = q & 7;
        swzA[i] = r * 128 + ((c ^ (r & 7)) * 16);
        gA[i] = A + (size_t)(aRow0 + r) * K + c * 16;
    }
#pragma unroll
    for (int i = 0; i < 4; i++) {
        int q = tid + i * 512, r = q >> 3, c = q & 7;
        swzB[i] = r * 128 + ((c ^ (r & 7)) * 16);
        gB[i] = Bt + (size_t)(bRow0 + r) * K + c * 16;
    }

#define LOAD_STAGE(s, kI) do {                                              \
    uint32_t _stA = sb + (s) * STAGE_BYTES;                                 \
    uint32_t _stB = _stA + A_BYTES;                                         \
    int _k0 = (kI) * KBLK;                                                  \
    _Pragma("unroll")                                                       \
    for (int _i = 0; _i < 2; _i++) cp16(_stA + swzA[_i], gA[_i] + _k0);     \
    _Pragma("unroll")                                                       \
    for (int _i = 0; _i < 4; _i++) cp16(_stB + swzB[_i], gB[_i] + _k0);     \
} while (0)

    // ldmatrix per-lane address components (16B chunk = 16 s8 = k16 half-step)
    const int rowLow = lane & 7;                  // row % 8 (swizzle selector)
    const int tau = lane >> 3;                    // tile index within x4
    // A frags: t0 rows+0 k-lo16, t1 rows+8 k-lo16, t2 rows+0 k-hi16, t3 rows+8 k-hi16
    const int rA = warpM + (tau & 1) * 8 + rowLow;
    const int hiA = tau >> 1;
    // B frags: t0 n+0 k-lo16, t1 n+0 k-hi16, t2 n+8 k-lo16, t3 n+8 k-hi16
    const int rB = warpN + (tau >> 1) * 8 + rowLow;
    const int hiB = tau & 1;

    int acc[2][8][4];
#pragma unroll
    for (int m = 0; m < 2; m++)
#pragma unroll
        for (int n = 0; n < 8; n++)
#pragma unroll
            for (int v = 0; v < 4; v++) acc[m][n][v] = 0;

    // fragment buffers (double-buffered across k32 steps)
    uint32_t af[2][2][4];   // [buf][mt][4]
    uint32_t bf[2][4][4];   // [buf][pair][4]

#define LD_FRAGS(buf, aB, bB, ks) do {                                        \
    _Pragma("unroll")                                                         \
    for (int _mt = 0; _mt < 2; _mt++) {                                       \
        uint32_t _ad = (aB) + (rA + _mt * 16) * 128 +                         \
                       (((2 * (ks) + hiA) ^ rowLow) * 16);                    \
        ldsm4(af[buf][_mt][0], af[buf][_mt][1], af[buf][_mt][2],              \
              af[buf][_mt][3], _ad);                                          \
    }                                                                         \
    _Pragma("unroll")                                                         \
    for (int _p = 0; _p < 4; _p++) {                                          \
        uint32_t _bd = (bB) + (rB + _p * 16) * 128 +                          \
                       (((2 * (ks) + hiB) ^ rowLow) * 16);                    \
        ldsm4(bf[buf][_p][0], bf[buf][_p][1], bf[buf][_p][2],                 \
              bf[buf][_p][3], _bd);                                           \
    }                                                                         \
} while (0)

#define DO_MMAS(buf) do {                                                     \
    _Pragma("unroll")                                                         \
    for (int _mt = 0; _mt < 2; _mt++)                                         \
        _Pragma("unroll")                                                     \
        for (int _nt = 0; _nt < 8; _nt++)                                     \
            mma_s8(acc[_mt][_nt], af[buf][_mt],                               \
                   &bf[buf][_nt >> 1][(_nt & 1) * 2]);                        \
} while (0)

    // prologue: fill NS-1 stages
#pragma unroll
    for (int p = 0; p < NS - 1; p++) { LOAD_STAGE(p, p); CP_COMMIT(); }

    for (int kb = 0; kb < KT; kb++) {
        int kp = kb + NS - 1;
        if (kp < KT) LOAD_STAGE(kp % NS, kp);
        CP_COMMIT();
        CP_WAIT(NS - 2);
        __syncthreads();

        const uint32_t aBase = sb + (kb % NS) * STAGE_BYTES;
        const uint32_t bBase = aBase + A_BYTES;

        LD_FRAGS(0, aBase, bBase, 0);
#pragma unroll
        for (int ks = 0; ks < 4; ks++) {          // 4 k32 steps per 128-elem block
            int cur = ks & 1;
            if (ks < 3) LD_FRAGS(!cur, aBase, bBase, ks + 1);
            DO_MMAS(cur);
        }
        __syncthreads();
    }
#undef LOAD_STAGE
#undef LD_FRAGS
#undef DO_MMAS

    // ---------------- epilogue (registers -> gmem) ----------------
    const int colW = cCol * BN + warpN;
#pragma unroll
    for (int mt = 0; mt < 2; mt++) {
        int r1 = aRow0 + warpM + mt * 16 + (lane >> 2);
        int r2 = r1 + 8;
        int tok1 = 0, tok2 = 0; float sc1 = 0.f, sc2 = 0.f;
        if (EP == 1) {
            tok1 = g_slot_token[r1];
            tok2 = g_slot_token[r2];
            if (tok1 >= 0) sc1 = g_top1_prob[tok1];
            if (tok2 >= 0) sc2 = g_top1_prob[tok2];
        }
#pragma unroll
        for (int nt = 0; nt < 8; nt++) {
            int col = colW + nt * 8 + 2 * (lane & 3);
            const float* bp = bias + expert * NTOT + col;
            float b0 = bp[0], b1 = bp[1];
            if (EP == 0) {
                float h0 = fmaxf((float)acc[mt][nt][0] * INV_XW1 + b0, 0.f) * HSCALE;
                float h1 = fmaxf((float)acc[mt][nt][1] * INV_XW1 + b1, 0.f) * HSCALE;
                float h2 = fmaxf((float)acc[mt][nt][2] * INV_XW1 + b0, 0.f) * HSCALE;
                float h3 = fmaxf((float)acc[mt][nt][3] * INV_XW1 + b1, 0.f) * HSCALE;
                g_H[(size_t)r1 * NTOT + col + 0] = (int8_t)q8i(h0);
                g_H[(size_t)r1 * NTOT + col + 1] = (int8_t)q8i(h1);
                g_H[(size_t)r2 * NTOT + col + 0] = (int8_t)q8i(h2);
                g_H[(size_t)r2 * NTOT + col + 1] = (int8_t)q8i(h3);
            } else {
                if (tok1 >= 0) {
                    float2 v;
                    v.x = ((float)acc[mt][nt][0] * INV_HW2 + b0) * sc1;
                    v.y = ((float)acc[mt][nt][1] * INV_HW2 + b1) * sc1;
                    *reinterpret_cast<float2*>(outp + (size_t)tok1 * NTOT + col) = v;
                }
                if (tok2 >= 0) {
                    float2 v;
                    v.x = ((float)acc[mt][nt][2] * INV_HW2 + b0) * sc2;
                    v.y = ((float)acc[mt][nt][3] * INV_HW2 + b1) * sc2;
                    *reinterpret_cast<float2*>(outp + (size_t)tok2 * NTOT + col) = v;
                }
            }
        }
    }
}

// ---------------- aux loss --------------------------------------------------
__global__ void finalize_kernel(float* out_scalar) {
    float dot = 0.f;
#pragma unroll
    for (int e = 0; e < NE; e++)
        dot += ((float)g_counts[e] / (float)TK) * (g_Pi[e] / (float)TK);
    float aux = 0.01f * (float)NE * dot + 0.001f * (g_zsum / (float)TK);
    *out_scalar = aux;
}

// ---------------- launch ----------------------------------------------------
extern "C" void kernel_launch(void* const* d_in, const int* in_sizes, int n_in,
                              void* d_out, int out_size) {
    const float* x  = (const float*)d_in[0];
    const float* wr = (const float*)d_in[1];
    const float* w1 = (const float*)d_in[2];
    const float* b1 = (const float*)d_in[3];
    const float* w2 = (const float*)d_in[4];
    const float* b2 = (const float*)d_in[5];
    float* out = (float*)d_out;

    cudaFuncSetAttribute(moe_gemm<DM, DF, 0>,
                         cudaFuncAttributeMaxDynamicSharedMemorySize, SMEM_TOTAL);
    cudaFuncSetAttribute(moe_gemm<DF, DM, 1>,
                         cudaFuncAttributeMaxDynamicSharedMemorySize, SMEM_TOTAL);

    int8_t* w1t; cudaGetSymbolAddress((void**)&w1t, g_W1t);
    int8_t* w2t; cudaGetSymbolAddress((void**)&w2t, g_W2t);

    init_kernel<<<(NE * CAPC + 255) / 256, 256>>>();
    router_kernel<<<256, 256>>>(x, wr);
    assign_kernel<<<1, 256>>>();
    dispatch_kernel<<<NE * CAPC, 256>>>(x);

    transpose_kernel<<<dim3(DF / 32, DM / 32, NE), dim3(32, 8)>>>(w1, w1t, DM, DF, W1SCALE);
    transpose_kernel<<<dim3(DM / 32, DF / 32, NE), dim3(32, 8)>>>(w2, w2t, DF, DM, W2SCALE);

    // GEMM1: H = relu(Xe * W1 + b1)   [16384 x 4096], K=1024
    moe_gemm<DM, DF, 0><<<dim3(DF / BN, TK / BM), 512, SMEM_TOTAL>>>(w1t, b1, nullptr);
    // GEMM2: out[t] = (H * W2 + b2) * prob, K=4096
    moe_gemm<DF, DM, 1><<<dim3(DM / BN, TK / BM), 512, SMEM_TOTAL>>>(w2t, b2, out);

    // passthrough for dropped tokens (gemm2 wrote all fitted tokens)
    dropped_copy_kernel<<<TK, 256>>>(x, out);

    if (out_size > TK * DM)
        finalize_kernel<<<1, 1>>>(out + (size_t)TK * DM);
}

// round 13
// speedup vs baseline: 2.6591x; 2.6591x over previous
#include <cuda_runtime.h>
#include <cuda_bf16.h>
#include <math.h>
#include <stdint.h>

// Problem constants
#define TK   16384        // total tokens (8 * 2048)
#define DM   1024         // d_model
#define DF   4096         // d_ff
#define NE   8            // experts
#define CAPC 2048         // capacity

// GEMM tiling (bf16 mma.sync, 2 CTAs/SM)
#define BM   128
#define BN   128
#define KBLK 64                         // K elems per stage: 64 bf16 = 128B row
#define NS   3                          // cp.async pipeline stages
#define A_BYTES (BM * 128)              // 16384
#define B_BYTES (BN * 128)              // 16384
#define STAGE_BYTES (A_BYTES + B_BYTES) // 32768
#define SMEM_TOTAL (NS * STAGE_BYTES)   // 98304 -> 2 CTAs/SM

// ---------------- scratch ---------------------------------------------------
__device__ __nv_bfloat16 g_expert_in[(size_t)NE * CAPC * DM];  // dispatched tokens
__device__ __nv_bfloat16 g_H[(size_t)TK * DF];                 // hidden acts
__device__ __nv_bfloat16 g_W1t[(size_t)NE * DF * DM];          // W1^T [E][4096][1024]
__device__ __nv_bfloat16 g_W2t[(size_t)NE * DM * DF];          // W2^T [E][1024][4096]
__device__ int   g_slot_token[NE * CAPC];
__device__ int   g_top1_idx[TK];
__device__ float g_top1_prob[TK];
__device__ int   g_fits[TK];
__device__ float g_Pi[NE];
__device__ float g_zsum;
__device__ int   g_counts[NE];

// ---------------- helpers ---------------------------------------------------
__device__ __forceinline__ uint32_t smem_u32(const void* p) {
    uint32_t a;
    asm("{ .reg .u64 t; cvta.to.shared.u64 t, %1; cvt.u32.u64 %0, t; }" : "=r"(a) : "l"(p));
    return a;
}
__device__ __forceinline__ uint32_t pack_bf2(float a, float b) {
    __nv_bfloat162 t = __floats2bfloat162_rn(a, b);
    return *reinterpret_cast<uint32_t*>(&t);
}
__device__ __forceinline__ void cp16(uint32_t sm, const void* g) {
    asm volatile("cp.async.cg.shared.global [%0], [%1], 16;" :: "r"(sm), "l"(g));
}
#define CP_COMMIT() asm volatile("cp.async.commit_group;" ::: "memory")
#define CP_WAIT(n)  asm volatile("cp.async.wait_group %0;" :: "n"(n) : "memory")

__device__ __forceinline__ void ldsm4(uint32_t& r0, uint32_t& r1, uint32_t& r2,
                                      uint32_t& r3, uint32_t addr) {
    asm volatile("ldmatrix.sync.aligned.m8n8.x4.shared.b16 {%0,%1,%2,%3}, [%4];"
                 : "=r"(r0), "=r"(r1), "=r"(r2), "=r"(r3) : "r"(addr));
}
__device__ __forceinline__ void mma_bf16(float* d, const uint32_t* a, const uint32_t* b) {
    asm volatile(
        "mma.sync.aligned.m16n8k16.row.col.f32.bf16.bf16.f32 "
        "{%0,%1,%2,%3}, {%4,%5,%6,%7}, {%8,%9}, {%0,%1,%2,%3};"
        : "+f"(d[0]), "+f"(d[1]), "+f"(d[2]), "+f"(d[3])
        : "r"(a[0]), "r"(a[1]), "r"(a[2]), "r"(a[3]), "r"(b[0]), "r"(b[1]));
}

// ---------------- init ------------------------------------------------------
__global__ void init_kernel() {
    int i = blockIdx.x * blockDim.x + threadIdx.x;
    if (i < NE * CAPC) g_slot_token[i] = -1;
    if (i < NE) g_Pi[i] = 0.f;
    if (i == 0) g_zsum = 0.f;
}

// ---------------- router ----------------------------------------------------
__global__ void router_kernel(const float* __restrict__ x,
                              const float* __restrict__ wr) {
    __shared__ float s_wr[DM * NE];
    __shared__ float s_pi[NE];
    __shared__ float s_z;
    for (int i = threadIdx.x; i < DM * NE; i += blockDim.x) s_wr[i] = wr[i];
    if (threadIdx.x < NE) s_pi[threadIdx.x] = 0.f;
    if (threadIdx.x == 0) s_z = 0.f;
    __syncthreads();

    int warp = threadIdx.x >> 5, lane = threadIdx.x & 31;
    int gw = blockIdx.x * (blockDim.x >> 5) + warp;
    int nw = gridDim.x * (blockDim.x >> 5);
    for (int t = gw; t < TK; t += nw) {
        const float* xt = x + (size_t)t * DM;
        float acc[NE];
#pragma unroll
        for (int e = 0; e < NE; e++) acc[e] = 0.f;
        for (int k = lane; k < DM; k += 32) {
            float xv = xt[k];
#pragma unroll
            for (int e = 0; e < NE; e++) acc[e] += xv * s_wr[k * NE + e];
        }
#pragma unroll
        for (int e = 0; e < NE; e++) {
#pragma unroll
            for (int off = 16; off; off >>= 1)
                acc[e] += __shfl_xor_sync(0xffffffffu, acc[e], off);
        }
        if (lane == 0) {
            float mx = acc[0]; int mi = 0;
#pragma unroll
            for (int e = 1; e < NE; e++) if (acc[e] > mx) { mx = acc[e]; mi = e; }
            float p[NE]; float se = 0.f;
#pragma unroll
            for (int e = 0; e < NE; e++) { p[e] = expf(acc[e] - mx); se += p[e]; }
            float inv = 1.f / se;
            g_top1_idx[t]  = mi;
            g_top1_prob[t] = inv;
#pragma unroll
            for (int e = 0; e < NE; e++) atomicAdd(&s_pi[e], p[e] * inv);
            float lse = mx + logf(se);
            atomicAdd(&s_z, lse * lse);
        }
    }
    __syncthreads();
    if (threadIdx.x < NE) atomicAdd(&g_Pi[threadIdx.x], s_pi[threadIdx.x]);
    if (threadIdx.x == 32) atomicAdd(&g_zsum, s_z);
}

// ---------------- FCFS capacity assignment ---------------------------------
__global__ void assign_kernel() {
    __shared__ int s_cnt[256 * NE];
    int tid = threadIdx.x;
#pragma unroll
    for (int e = 0; e < NE; e++) s_cnt[tid * NE + e] = 0;
    const int CHUNK = TK / 256;
    int base = tid * CHUNK;
    for (int i = 0; i < CHUNK; i++) s_cnt[tid * NE + g_top1_idx[base + i]]++;
    __syncthreads();
    if (tid < NE) {
        int run = 0;
        for (int i = 0; i < 256; i++) {
            int v = s_cnt[i * NE + tid];
            s_cnt[i * NE + tid] = run;
            run += v;
        }
        g_counts[tid] = run;
    }
    __syncthreads();
    for (int i = 0; i < CHUNK; i++) {
        int t = base + i;
        int e = g_top1_idx[t];
        int p = s_cnt[tid * NE + e]++;
        int f = (p < CAPC);
        g_fits[t] = f;
        if (f) g_slot_token[e * CAPC + p] = t;
    }
}

// ---------------- dispatch (fp32 -> bf16) ------------------------------------
__global__ void dispatch_kernel(const float* __restrict__ x) {
    int s = blockIdx.x;
    int t = g_slot_token[s];
    uint2* dst = reinterpret_cast<uint2*>(g_expert_in + (size_t)s * DM);
    if (t >= 0) {
        float4 v = reinterpret_cast<const float4*>(x + (size_t)t * DM)[threadIdx.x];
        uint2 o;
        o.x = pack_bf2(v.x, v.y);
        o.y = pack_bf2(v.z, v.w);
        dst[threadIdx.x] = o;
    } else {
        dst[threadIdx.x] = make_uint2(0u, 0u);
    }
}

// ---------------- passthrough for dropped tokens only -----------------------
__global__ void dropped_copy_kernel(const float* __restrict__ x, float* __restrict__ out) {
    int t = blockIdx.x;
    if (g_fits[t]) return;
    reinterpret_cast<float4*>(out + (size_t)t * DM)[threadIdx.x] =
        reinterpret_cast<const float4*>(x + (size_t)t * DM)[threadIdx.x];
}

// ---------------- weight transpose [E][K][N] -> [E][N][K] bf16 --------------
__global__ void transpose_kernel(const float* __restrict__ src,
                                 __nv_bfloat16* __restrict__ dst,
                                 int K, int N) {
    __shared__ float tile[32][33];
    int e = blockIdx.z;
    int k0 = blockIdx.y * 32, n0 = blockIdx.x * 32;
    src += (size_t)e * K * N;
    dst += (size_t)e * N * K;
#pragma unroll
    for (int i = threadIdx.y; i < 32; i += 8)
        tile[i][threadIdx.x] = src[(size_t)(k0 + i) * N + n0 + threadIdx.x];
    __syncthreads();
#pragma unroll
    for (int i = threadIdx.y; i < 32; i += 8)
        dst[(size_t)(n0 + i) * K + k0 + threadIdx.x] =
            __float2bfloat16_rn(tile[threadIdx.x][i]);
}

// ---------------- bf16 mma.sync GEMM, 2 CTAs/SM ------------------------------
// C[16384, NTOT] = A[16384, K] * Bt_e[NTOT, K]^T  (per-expert weights, bf16)
// CTA 128x128; 8 warps in 4x2 grid, each 32x64. k-block = 64 elems (128B row).
// EP=0: H = bf16(relu(Xe*W1+b1)); EP=1: scatter (H*W2+b2)*prob -> out (fp32)
template <int K, int NTOT, int EP>
__global__ __launch_bounds__(256, 2) void moe_gemm(
    const __nv_bfloat16* __restrict__ Bt, const float* __restrict__ bias,
    float* __restrict__ outp) {
    extern __shared__ char smem[];
    const uint32_t sb = smem_u32(smem);
    const int tid = threadIdx.x, wid = tid >> 5, lane = tid & 31;
    constexpr int KT = K / KBLK;

    const __nv_bfloat16* A = (EP == 0) ? g_expert_in : g_H;
    const int cCol = blockIdx.x, cRow = blockIdx.y;
    const int expert = cRow >> 4;                 // 2048 rows / 128 per expert
    const int aRow0 = cRow * BM;
    const int bRow0 = expert * NTOT + cCol * BN;
    const int warpM = (wid >> 1) * 32;            // 0,32,64,96
    const int warpN = (wid & 1) * 64;             // 0,64

    // cp.async per-thread pattern: 16B chunks (8 bf16), swizzled smem targets
    // 256 threads: A = 4 chunks, B = 4 chunks per stage
    uint32_t swzA[4], swzB[4];
    const __nv_bfloat16* gA[4];
    const __nv_bfloat16* gB[4];
#pragma unroll
    for (int i = 0; i < 4; i++) {
        int q = tid + i * 256, r = q >> 3, c = q & 7;
        swzA[i] = r * 128 + ((c ^ (r & 7)) * 16);
        gA[i] = A + (size_t)(aRow0 + r) * K + c * 8;
        swzB[i] = swzA[i];
        gB[i] = Bt + (size_t)(bRow0 + r) * K + c * 8;
    }

#define LOAD_STAGE(s, kI) do {                                              \
    uint32_t _stA = sb + (s) * STAGE_BYTES;                                 \
    uint32_t _stB = _stA + A_BYTES;                                         \
    int _k0 = (kI) * KBLK;                                                  \
    _Pragma("unroll")                                                       \
    for (int _i = 0; _i < 4; _i++) {                                        \
        cp16(_stA + swzA[_i], gA[_i] + _k0);                                \
        cp16(_stB + swzB[_i], gB[_i] + _k0);                                \
    }                                                                       \
} while (0)

    // ldmatrix per-lane address components
    const int rowLow = lane & 7;                  // row % 8 (swizzle selector)
    const int tau = lane >> 3;                    // tile index within x4
    const int rA = warpM + (tau & 1) * 8 + rowLow;
    const int hiA = tau >> 1;
    const int rB = warpN + (tau >> 1) * 8 + rowLow;
    const int hiB = tau & 1;

    float acc[2][8][4];
#pragma unroll
    for (int m = 0; m < 2; m++)
#pragma unroll
        for (int n = 0; n < 8; n++)
#pragma unroll
            for (int v = 0; v < 4; v++) acc[m][n][v] = 0.f;

    // prologue: fill NS-1 stages
#pragma unroll
    for (int p = 0; p < NS - 1; p++) { LOAD_STAGE(p, p); CP_COMMIT(); }

    for (int kb = 0; kb < KT; kb++) {
        int kp = kb + NS - 1;
        if (kp < KT) LOAD_STAGE(kp % NS, kp);
        CP_COMMIT();
        CP_WAIT(NS - 2);
        __syncthreads();

        const uint32_t aBase = sb + (kb % NS) * STAGE_BYTES;
        const uint32_t bBase = aBase + A_BYTES;
#pragma unroll
        for (int ks = 0; ks < 4; ks++) {          // 4 k16 steps per 64-elem block
            uint32_t af[2][4];
#pragma unroll
            for (int mt = 0; mt < 2; mt++) {
                uint32_t ad = aBase + (rA + mt * 16) * 128 +
                              (((2 * ks + hiA) ^ rowLow) * 16);
                ldsm4(af[mt][0], af[mt][1], af[mt][2], af[mt][3], ad);
            }
            uint32_t bf[4][4];                    // pair p covers n-tiles 2p,2p+1
#pragma unroll
            for (int p = 0; p < 4; p++) {
                uint32_t bd = bBase + (rB + p * 16) * 128 +
                              (((2 * ks + hiB) ^ rowLow) * 16);
                ldsm4(bf[p][0], bf[p][1], bf[p][2], bf[p][3], bd);
            }
#pragma unroll
            for (int mt = 0; mt < 2; mt++)
#pragma unroll
                for (int nt = 0; nt < 8; nt++)
                    mma_bf16(acc[mt][nt], af[mt], &bf[nt >> 1][(nt & 1) * 2]);
        }
        __syncthreads();
    }
#undef LOAD_STAGE

    // ---------------- epilogue (registers -> gmem) ----------------
    const int colW = cCol * BN + warpN;
#pragma unroll
    for (int mt = 0; mt < 2; mt++) {
        int r1 = aRow0 + warpM + mt * 16 + (lane >> 2);
        int r2 = r1 + 8;
        int tok1 = 0, tok2 = 0; float sc1 = 0.f, sc2 = 0.f;
        if (EP == 1) {
            tok1 = g_slot_token[r1];
            tok2 = g_slot_token[r2];
            if (tok1 >= 0) sc1 = g_top1_prob[tok1];
            if (tok2 >= 0) sc2 = g_top1_prob[tok2];
        }
#pragma unroll
        for (int nt = 0; nt < 8; nt++) {
            int col = colW + nt * 8 + 2 * (lane & 3);
            const float* bp = bias + expert * NTOT + col;
            float b0 = bp[0], b1 = bp[1];
            if (EP == 0) {
                uint32_t v1 = pack_bf2(fmaxf(acc[mt][nt][0] + b0, 0.f),
                                       fmaxf(acc[mt][nt][1] + b1, 0.f));
                uint32_t v2 = pack_bf2(fmaxf(acc[mt][nt][2] + b0, 0.f),
                                       fmaxf(acc[mt][nt][3] + b1, 0.f));
                *reinterpret_cast<uint32_t*>(&g_H[(size_t)r1 * NTOT + col]) = v1;
                *reinterpret_cast<uint32_t*>(&g_H[(size_t)r2 * NTOT + col]) = v2;
            } else {
                if (tok1 >= 0) {
                    float2 v;
                    v.x = (acc[mt][nt][0] + b0) * sc1;
                    v.y = (acc[mt][nt][1] + b1) * sc1;
                    *reinterpret_cast<float2*>(outp + (size_t)tok1 * NTOT + col) = v;
                }
                if (tok2 >= 0) {
                    float2 v;
                    v.x = (acc[mt][nt][2] + b0) * sc2;
                    v.y = (acc[mt][nt][3] + b1) * sc2;
                    *reinterpret_cast<float2*>(outp + (size_t)tok2 * NTOT + col) = v;
                }
            }
        }
    }
}

// ---------------- aux loss --------------------------------------------------
__global__ void finalize_kernel(float* out_scalar) {
    float dot = 0.f;
#pragma unroll
    for (int e = 0; e < NE; e++)
        dot += ((float)g_counts[e] / (float)TK) * (g_Pi[e] / (float)TK);
    float aux = 0.01f * (float)NE * dot + 0.001f * (g_zsum / (float)TK);
    *out_scalar = aux;
}

// ---------------- launch ----------------------------------------------------
extern "C" void kernel_launch(void* const* d_in, const int* in_sizes, int n_in,
                              void* d_out, int out_size) {
    const float* x  = (const float*)d_in[0];
    const float* wr = (const float*)d_in[1];
    const float* w1 = (const float*)d_in[2];
    const float* b1 = (const float*)d_in[3];
    const float* w2 = (const float*)d_in[4];
    const float* b2 = (const float*)d_in[5];
    float* out = (float*)d_out;

    cudaFuncSetAttribute(moe_gemm<DM, DF, 0>,
                         cudaFuncAttributeMaxDynamicSharedMemorySize, SMEM_TOTAL);
    cudaFuncSetAttribute(moe_gemm<DF, DM, 1>,
                         cudaFuncAttributeMaxDynamicSharedMemorySize, SMEM_TOTAL);

    __nv_bfloat16* w1t; cudaGetSymbolAddress((void**)&w1t, g_W1t);
    __nv_bfloat16* w2t; cudaGetSymbolAddress((void**)&w2t, g_W2t);

    init_kernel<<<(NE * CAPC + 255) / 256, 256>>>();
    router_kernel<<<256, 256>>>(x, wr);
    assign_kernel<<<1, 256>>>();
    dispatch_kernel<<<NE * CAPC, 256>>>(x);

    transpose_kernel<<<dim3(DF / 32, DM / 32, NE), dim3(32, 8)>>>(w1, w1t, DM, DF);
    transpose_kernel<<<dim3(DM / 32, DF / 32, NE), dim3(32, 8)>>>(w2, w2t, DF, DM);

    // GEMM1: H = relu(Xe * W1 + b1)   [16384 x 4096], K=1024
    moe_gemm<DM, DF, 0><<<dim3(DF / BN, TK / BM), 256, SMEM_TOTAL>>>(w1t, b1, nullptr);
    // GEMM2: out[t] = (H * W2 + b2) * prob, K=4096
    moe_gemm<DF, DM, 1><<<dim3(DM / BN, TK / BM), 256, SMEM_TOTAL>>>(w2t, b2, out);

    // passthrough for dropped tokens (gemm2 wrote all fitted tokens)
    dropped_copy_kernel<<<TK, 256>>>(x, out);

    if (out_size > TK * DM)
        finalize_kernel<<<1, 1>>>(out + (size_t)TK * DM);
}

// round 15
// speedup vs baseline: 2.7467x; 1.0330x over previous
#include <cuda_runtime.h>
#include <cuda_bf16.h>
#include <math.h>
#include <stdint.h>

// Problem constants
#define TK   16384        // total tokens (8 * 2048)
#define DM   1024         // d_model
#define DF   4096         // d_ff
#define NE   8            // experts
#define CAPC 2048         // capacity

// GEMM tiling (bf16 mma.sync; BM fixed 128, BN templated)
#define BM   128
#define KBLK 64                         // K elems per stage: 64 bf16 = 128B row
#define NS   3                          // cp.async pipeline stages
#define A_BYTES (BM * 128)              // 16384
#define SMEM_G1 (NS * (A_BYTES + 128 * 128))   // 98304  (BN=128)
#define SMEM_G2 (NS * (A_BYTES + 64 * 128))    // 73728  (BN=64)

// ---------------- scratch ---------------------------------------------------
__device__ __nv_bfloat16 g_expert_in[(size_t)NE * CAPC * DM];  // dispatched tokens
__device__ __nv_bfloat16 g_H[(size_t)TK * DF];                 // hidden acts
__device__ __nv_bfloat16 g_W1t[(size_t)NE * DF * DM];          // W1^T [E][4096][1024]
__device__ __nv_bfloat16 g_W2t[(size_t)NE * DM * DF];          // W2^T [E][1024][4096]
__device__ int   g_slot_token[NE * CAPC];
__device__ int   g_top1_idx[TK];
__device__ float g_top1_prob[TK];
__device__ int   g_fits[TK];
__device__ float g_Pi[NE];
__device__ float g_zsum;
__device__ int   g_counts[NE];

// ---------------- helpers ---------------------------------------------------
__device__ __forceinline__ uint32_t smem_u32(const void* p) {
    uint32_t a;
    asm("{ .reg .u64 t; cvta.to.shared.u64 t, %1; cvt.u32.u64 %0, t; }" : "=r"(a) : "l"(p));
    return a;
}
__device__ __forceinline__ uint32_t pack_bf2(float a, float b) {
    __nv_bfloat162 t = __floats2bfloat162_rn(a, b);
    return *reinterpret_cast<uint32_t*>(&t);
}
__device__ __forceinline__ void cp16(uint32_t sm, const void* g) {
    asm volatile("cp.async.cg.shared.global [%0], [%1], 16;" :: "r"(sm), "l"(g));
}
#define CP_COMMIT() asm volatile("cp.async.commit_group;" ::: "memory")
#define CP_WAIT(n)  asm volatile("cp.async.wait_group %0;" :: "n"(n) : "memory")

__device__ __forceinline__ void ldsm4(uint32_t& r0, uint32_t& r1, uint32_t& r2,
                                      uint32_t& r3, uint32_t addr) {
    asm volatile("ldmatrix.sync.aligned.m8n8.x4.shared.b16 {%0,%1,%2,%3}, [%4];"
                 : "=r"(r0), "=r"(r1), "=r"(r2), "=r"(r3) : "r"(addr));
}
__device__ __forceinline__ void mma_bf16(float* d, const uint32_t* a, const uint32_t* b) {
    asm volatile(
        "mma.sync.aligned.m16n8k16.row.col.f32.bf16.bf16.f32 "
        "{%0,%1,%2,%3}, {%4,%5,%6,%7}, {%8,%9}, {%0,%1,%2,%3};"
        : "+f"(d[0]), "+f"(d[1]), "+f"(d[2]), "+f"(d[3])
        : "r"(a[0]), "r"(a[1]), "r"(a[2]), "r"(a[3]), "r"(b[0]), "r"(b[1]));
}

// ---------------- init ------------------------------------------------------
__global__ void init_kernel() {
    int i = blockIdx.x * blockDim.x + threadIdx.x;
    if (i < NE * CAPC) g_slot_token[i] = -1;
    if (i < NE) g_Pi[i] = 0.f;
    if (i == 0) g_zsum = 0.f;
}

// ---------------- router ----------------------------------------------------
__global__ void router_kernel(const float* __restrict__ x,
                              const float* __restrict__ wr) {
    __shared__ float s_wr[DM * NE];
    __shared__ float s_pi[NE];
    __shared__ float s_z;
    for (int i = threadIdx.x; i < DM * NE; i += blockDim.x) s_wr[i] = wr[i];
    if (threadIdx.x < NE) s_pi[threadIdx.x] = 0.f;
    if (threadIdx.x == 0) s_z = 0.f;
    __syncthreads();

    int warp = threadIdx.x >> 5, lane = threadIdx.x & 31;
    int gw = blockIdx.x * (blockDim.x >> 5) + warp;
    int nw = gridDim.x * (blockDim.x >> 5);
    for (int t = gw; t < TK; t += nw) {
        const float* xt = x + (size_t)t * DM;
        float acc[NE];
#pragma unroll
        for (int e = 0; e < NE; e++) acc[e] = 0.f;
        for (int k = lane; k < DM; k += 32) {
            float xv = xt[k];
#pragma unroll
            for (int e = 0; e < NE; e++) acc[e] += xv * s_wr[k * NE + e];
        }
#pragma unroll
        for (int e = 0; e < NE; e++) {
#pragma unroll
            for (int off = 16; off; off >>= 1)
                acc[e] += __shfl_xor_sync(0xffffffffu, acc[e], off);
        }
        if (lane == 0) {
            float mx = acc[0]; int mi = 0;
#pragma unroll
            for (int e = 1; e < NE; e++) if (acc[e] > mx) { mx = acc[e]; mi = e; }
            float p[NE]; float se = 0.f;
#pragma unroll
            for (int e = 0; e < NE; e++) { p[e] = expf(acc[e] - mx); se += p[e]; }
            float inv = 1.f / se;
            g_top1_idx[t]  = mi;
            g_top1_prob[t] = inv;
#pragma unroll
            for (int e = 0; e < NE; e++) atomicAdd(&s_pi[e], p[e] * inv);
            float lse = mx + logf(se);
            atomicAdd(&s_z, lse * lse);
        }
    }
    __syncthreads();
    if (threadIdx.x < NE) atomicAdd(&g_Pi[threadIdx.x], s_pi[threadIdx.x]);
    if (threadIdx.x == 32) atomicAdd(&g_zsum, s_z);
}

// ---------------- FCFS capacity assignment ---------------------------------
__global__ void assign_kernel() {
    __shared__ int s_cnt[256 * NE];
    int tid = threadIdx.x;
#pragma unroll
    for (int e = 0; e < NE; e++) s_cnt[tid * NE + e] = 0;
    const int CHUNK = TK / 256;
    int base = tid * CHUNK;
    for (int i = 0; i < CHUNK; i++) s_cnt[tid * NE + g_top1_idx[base + i]]++;
    __syncthreads();
    if (tid < NE) {
        int run = 0;
        for (int i = 0; i < 256; i++) {
            int v = s_cnt[i * NE + tid];
            s_cnt[i * NE + tid] = run;
            run += v;
        }
        g_counts[tid] = run;
    }
    __syncthreads();
    for (int i = 0; i < CHUNK; i++) {
        int t = base + i;
        int e = g_top1_idx[t];
        int p = s_cnt[tid * NE + e]++;
        int f = (p < CAPC);
        g_fits[t] = f;
        if (f) g_slot_token[e * CAPC + p] = t;
    }
}

// ---------------- dispatch (fp32 -> bf16) ------------------------------------
__global__ void dispatch_kernel(const float* __restrict__ x) {
    int s = blockIdx.x;
    int t = g_slot_token[s];
    uint2* dst = reinterpret_cast<uint2*>(g_expert_in + (size_t)s * DM);
    if (t >= 0) {
        float4 v = reinterpret_cast<const float4*>(x + (size_t)t * DM)[threadIdx.x];
        uint2 o;
        o.x = pack_bf2(v.x, v.y);
        o.y = pack_bf2(v.z, v.w);
        dst[threadIdx.x] = o;
    } else {
        dst[threadIdx.x] = make_uint2(0u, 0u);
    }
}

// ---------------- passthrough for dropped tokens only -----------------------
__global__ void dropped_copy_kernel(const float* __restrict__ x, float* __restrict__ out) {
    int t = blockIdx.x;
    if (g_fits[t]) return;
    reinterpret_cast<float4*>(out + (size_t)t * DM)[threadIdx.x] =
        reinterpret_cast<const float4*>(x + (size_t)t * DM)[threadIdx.x];
}

// ---------------- weight transpose [E][K][N] -> [E][N][K] bf16 --------------
// 64x64 tiles, 256 threads; 128B-coalesced reads (float2) and writes (bf16x2).
__global__ void transpose_kernel(const float* __restrict__ src,
                                 __nv_bfloat16* __restrict__ dst,
                                 int K, int N) {
    __shared__ float tile[64][65];
    int e = blockIdx.z;
    int k0 = blockIdx.y * 64, n0 = blockIdx.x * 64;
    src += (size_t)e * K * N;
    dst += (size_t)e * N * K;
    int tx = threadIdx.x, ty = threadIdx.y;   // 32 x 8
#pragma unroll
    for (int i = 0; i < 8; i++) {
        int r = ty + i * 8;
        float2 v = *reinterpret_cast<const float2*>(
            &src[(size_t)(k0 + r) * N + n0 + 2 * tx]);
        tile[r][2 * tx]     = v.x;
        tile[r][2 * tx + 1] = v.y;
    }
    __syncthreads();
#pragma unroll
    for (int i = 0; i < 8; i++) {
        int c = ty + i * 8;
        __nv_bfloat162 o = __floats2bfloat162_rn(tile[2 * tx][c], tile[2 * tx + 1][c]);
        *reinterpret_cast<__nv_bfloat162*>(
            &dst[(size_t)(n0 + c) * K + k0 + 2 * tx]) = o;
    }
}

// ---------------- bf16 mma.sync GEMM (templated BN) --------------------------
// C[16384, NTOT] = A[16384, K] * Bt_e[NTOT, K]^T  (per-expert weights, bf16)
// CTA 128xBNT; 8 warps in 4x2 grid, warp tile 32 x BNT/2.
// EP=0: H = bf16(relu(Xe*W1+b1)); EP=1: scatter (H*W2+b2)*prob -> out (fp32)
template <int K, int NTOT, int EP, int BNT, int MINB>
__global__ __launch_bounds__(256, MINB) void moe_gemm(
    const __nv_bfloat16* __restrict__ Bt, const float* __restrict__ bias,
    float* __restrict__ outp) {
    extern __shared__ char smem[];
    const uint32_t sb = smem_u32(smem);
    const int tid = threadIdx.x, wid = tid >> 5, lane = tid & 31;
    constexpr int KT = K / KBLK;
    constexpr int B_BYTES = BNT * 128;
    constexpr int STAGE_BYTES = A_BYTES + B_BYTES;
    constexpr int WN = BNT / 2;           // warp N tile
    constexpr int NP = WN / 16;           // B ldsm per k-step
    constexpr int NT = WN / 8;            // n-tiles per warp
    constexpr int NCHB = BNT / 32;        // B cp.async chunks per thread

    const __nv_bfloat16* A = (EP == 0) ? g_expert_in : g_H;
    const int cCol = blockIdx.x, cRow = blockIdx.y;
    const int expert = cRow >> 4;                 // 2048 rows / 128 per expert
    const int aRow0 = cRow * BM;
    const int bRow0 = expert * NTOT + cCol * BNT;
    const int warpM = (wid >> 1) * 32;            // 0,32,64,96
    const int warpN = (wid & 1) * WN;

    // cp.async per-thread pattern: 16B chunks (8 bf16), swizzled smem targets
    uint32_t swzA[4], swzB[NCHB];
    const __nv_bfloat16* gA[4];
    const __nv_bfloat16* gB[NCHB];
#pragma unroll
    for (int i = 0; i < 4; i++) {
        int q = tid + i * 256, r = q >> 3, c = q & 7;
        swzA[i] = r * 128 + ((c ^ (r & 7)) * 16);
        gA[i] = A + (size_t)(aRow0 + r) * K + c * 8;
    }
#pragma unroll
    for (int i = 0; i < NCHB; i++) {
        int q = tid + i * 256, r = q >> 3, c = q & 7;
        swzB[i] = r * 128 + ((c ^ (r & 7)) * 16);
        gB[i] = Bt + (size_t)(bRow0 + r) * K + c * 8;
    }

#define LOAD_STAGE(s, kI) do {                                              \
    uint32_t _stA = sb + (s) * STAGE_BYTES;                                 \
    uint32_t _stB = _stA + A_BYTES;                                         \
    int _k0 = (kI) * KBLK;                                                  \
    _Pragma("unroll")                                                       \
    for (int _i = 0; _i < 4; _i++) cp16(_stA + swzA[_i], gA[_i] + _k0);     \
    _Pragma("unroll")                                                       \
    for (int _i = 0; _i < NCHB; _i++) cp16(_stB + swzB[_i], gB[_i] + _k0);  \
} while (0)

    // ldmatrix per-lane address components
    const int rowLow = lane & 7;                  // row % 8 (swizzle selector)
    const int tau = lane >> 3;                    // tile index within x4
    const int rA = warpM + (tau & 1) * 8 + rowLow;
    const int hiA = tau >> 1;
    const int rB = warpN + (tau >> 1) * 8 + rowLow;
    const int hiB = tau & 1;

    float acc[2][NT][4];
#pragma unroll
    for (int m = 0; m < 2; m++)
#pragma unroll
        for (int n = 0; n < NT; n++)
#pragma unroll
            for (int v = 0; v < 4; v++) acc[m][n][v] = 0.f;

    // prologue: fill NS-1 stages
#pragma unroll
    for (int p = 0; p < NS - 1; p++) { LOAD_STAGE(p, p); CP_COMMIT(); }

    for (int kb = 0; kb < KT; kb++) {
        int kp = kb + NS - 1;
        if (kp < KT) LOAD_STAGE(kp % NS, kp);
        CP_COMMIT();
        CP_WAIT(NS - 2);
        __syncthreads();

        const uint32_t aBase = sb + (kb % NS) * STAGE_BYTES;
        const uint32_t bBase = aBase + A_BYTES;
#pragma unroll
        for (int ks = 0; ks < 4; ks++) {          // 4 k16 steps per 64-elem block
            uint32_t af[2][4];
#pragma unroll
            for (int mt = 0; mt < 2; mt++) {
                uint32_t ad = aBase + (rA + mt * 16) * 128 +
                              (((2 * ks + hiA) ^ rowLow) * 16);
                ldsm4(af[mt][0], af[mt][1], af[mt][2], af[mt][3], ad);
            }
            uint32_t bf[NP][4];                   // pair p covers n-tiles 2p,2p+1
#pragma unroll
            for (int p = 0; p < NP; p++) {
                uint32_t bd = bBase + (rB + p * 16) * 128 +
                              (((2 * ks + hiB) ^ rowLow) * 16);
                ldsm4(bf[p][0], bf[p][1], bf[p][2], bf[p][3], bd);
            }
#pragma unroll
            for (int mt = 0; mt < 2; mt++)
#pragma unroll
                for (int nt = 0; nt < NT; nt++)
                    mma_bf16(acc[mt][nt], af[mt], &bf[nt >> 1][(nt & 1) * 2]);
        }
        __syncthreads();
    }
#undef LOAD_STAGE

    // ---------------- epilogue (registers -> gmem) ----------------
    const int colW = cCol * BNT + warpN;
#pragma unroll
    for (int mt = 0; mt < 2; mt++) {
        int r1 = aRow0 + warpM + mt * 16 + (lane >> 2);
        int r2 = r1 + 8;
        int tok1 = 0, tok2 = 0; float sc1 = 0.f, sc2 = 0.f;
        if (EP == 1) {
            tok1 = g_slot_token[r1];
            tok2 = g_slot_token[r2];
            if (tok1 >= 0) sc1 = g_top1_prob[tok1];
            if (tok2 >= 0) sc2 = g_top1_prob[tok2];
        }
#pragma unroll
        for (int nt = 0; nt < NT; nt++) {
            int col = colW + nt * 8 + 2 * (lane & 3);
            const float* bp = bias + expert * NTOT + col;
            float b0 = bp[0], b1 = bp[1];
            if (EP == 0) {
                uint32_t v1 = pack_bf2(fmaxf(acc[mt][nt][0] + b0, 0.f),
                                       fmaxf(acc[mt][nt][1] + b1, 0.f));
                uint32_t v2 = pack_bf2(fmaxf(acc[mt][nt][2] + b0, 0.f),
                                       fmaxf(acc[mt][nt][3] + b1, 0.f));
                *reinterpret_cast<uint32_t*>(&g_H[(size_t)r1 * NTOT + col]) = v1;
                *reinterpret_cast<uint32_t*>(&g_H[(size_t)r2 * NTOT + col]) = v2;
            } else {
                if (tok1 >= 0) {
                    float2 v;
                    v.x = (acc[mt][nt][0] + b0) * sc1;
                    v.y = (acc[mt][nt][1] + b1) * sc1;
                    *reinterpret_cast<float2*>(outp + (size_t)tok1 * NTOT + col) = v;
                }
                if (tok2 >= 0) {
                    float2 v;
                    v.x = (acc[mt][nt][2] + b0) * sc2;
                    v.y = (acc[mt][nt][3] + b1) * sc2;
                    *reinterpret_cast<float2*>(outp + (size_t)tok2 * NTOT + col) = v;
                }
            }
        }
    }
}

// ---------------- aux loss --------------------------------------------------
__global__ void finalize_kernel(float* out_scalar) {
    float dot = 0.f;
#pragma unroll
    for (int e = 0; e < NE; e++)
        dot += ((float)g_counts[e] / (float)TK) * (g_Pi[e] / (float)TK);
    float aux = 0.01f * (float)NE * dot + 0.001f * (g_zsum / (float)TK);
    *out_scalar = aux;
}

// ---------------- launch ----------------------------------------------------
extern "C" void kernel_launch(void* const* d_in, const int* in_sizes, int n_in,
                              void* d_out, int out_size) {
    const float* x  = (const float*)d_in[0];
    const float* wr = (const float*)d_in[1];
    const float* w1 = (const float*)d_in[2];
    const float* b1 = (const float*)d_in[3];
    const float* w2 = (const float*)d_in[4];
    const float* b2 = (const float*)d_in[5];
    float* out = (float*)d_out;

    cudaFuncSetAttribute(moe_gemm<DM, DF, 0, 128, 2>,
                         cudaFuncAttributeMaxDynamicSharedMemorySize, SMEM_G1);
    cudaFuncSetAttribute(moe_gemm<DF, DM, 1, 64, 3>,
                         cudaFuncAttributeMaxDynamicSharedMemorySize, SMEM_G2);

    __nv_bfloat16* w1t; cudaGetSymbolAddress((void**)&w1t, g_W1t);
    __nv_bfloat16* w2t; cudaGetSymbolAddress((void**)&w2t, g_W2t);

    init_kernel<<<(NE * CAPC + 255) / 256, 256>>>();
    router_kernel<<<256, 256>>>(x, wr);
    assign_kernel<<<1, 256>>>();
    dispatch_kernel<<<NE * CAPC, 256>>>(x);

    transpose_kernel<<<dim3(DF / 64, DM / 64, NE), dim3(32, 8)>>>(w1, w1t, DM, DF);
    transpose_kernel<<<dim3(DM / 64, DF / 64, NE), dim3(32, 8)>>>(w2, w2t, DF, DM);

    // GEMM1: H = relu(Xe * W1 + b1)   [16384 x 4096], K=1024, BN=128
    moe_gemm<DM, DF, 0, 128, 2><<<dim3(DF / 128, TK / BM), 256, SMEM_G1>>>(w1t, b1, nullptr);
    // GEMM2: out[t] = (H * W2 + b2) * prob, K=4096, BN=64 (tail fix + 3 CTAs/SM)
    moe_gemm<DF, DM, 1, 64, 3><<<dim3(DM / 64, TK / BM), 256, SMEM_G2>>>(w2t, b2, out);

    // passthrough for dropped tokens (gemm2 wrote all fitted tokens)
    dropped_copy_kernel<<<TK, 256>>>(x, out);

    if (out_size > TK * DM)
        finalize_kernel<<<1, 1>>>(out + (size_t)TK * DM);
}